// round 10
// baseline (speedup 1.0000x reference)
#include <cuda_runtime.h>
#include <cuda_bf16.h>
#include <stdint.h>

// FuzzyPooling: 2x2 stride-2 pooling with fuzzy membership selection.
// x: (32,64,128,128) fp32 -> out: (32,64,64,64) fp32
//
// mu1 = tri(v,1.5,1.5); mu2 = tri(v,3.0,1.5); mu3 == mu2 (identical
// constants), argmax takes first max -> sel = (s1 >= s2) ? mu1 : mu2.
// Unnormalized memberships (scale-invariant use): u_c(v) = max(1.5-|v-c|,0).
//
// R9 = R8 (best: 24.0us, math-issue bound) with the FULL dataflow in
// packed f32x2 along the element axis:
//   - loads as ulonglong2 (lanes pre-packed, scalar a..d never built)
//   - w-adds, s-sums, m*v products, den/num reductions all packed
//   - only the per-lane membership clamp (FADD+FMNMX) and the final
//     horizontal lane-adds stay scalar
// ~24 fewer issue slots per thread (~12%).

#define N_OUT  (32 * 64 * 64 * 64)   // 8,388,608

typedef unsigned long long ull;

__device__ __forceinline__ ull f2_pack(float lo, float hi) {
    ull r; asm("mov.b64 %0, {%1, %2};" : "=l"(r) : "f"(lo), "f"(hi)); return r;
}
__device__ __forceinline__ float2 f2_unpack(ull p) {
    float2 v; asm("mov.b64 {%0, %1}, %2;" : "=f"(v.x), "=f"(v.y) : "l"(p)); return v;
}
__device__ __forceinline__ ull f2_add(ull a, ull b) {
    ull r; asm("add.rn.f32x2 %0, %1, %2;" : "=l"(r) : "l"(a), "l"(b)); return r;
}
__device__ __forceinline__ ull f2_mul(ull a, ull b) {
    ull r; asm("mul.rn.f32x2 %0, %1, %2;" : "=l"(r) : "l"(a), "l"(b)); return r;
}
__device__ __forceinline__ ull f2_fma(ull a, ull b, ull c) {
    ull r; asm("fma.rn.f32x2 %0, %1, %2, %3;" : "=l"(r) : "l"(a), "l"(b), "l"(c)); return r;
}

// packed pair of unnormalized memberships: per lane max(1.5 - |w|, 0)
__device__ __forceinline__ ull tri2(ull w) {
    float2 f = f2_unpack(w);
    float m0 = fmaxf(1.5f - fabsf(f.x), 0.0f);   // FADD(|.|) + FMNMX
    float m1 = fmaxf(1.5f - fabsf(f.y), 0.0f);
    return f2_pack(m0, m1);
}

__device__ __forceinline__ float fuzzy_patch(ull top, ull bot, ull C15, ull C30) {
    // memberships, packed along the element axis
    ull m1t = tri2(f2_add(top, C15));
    ull m2t = tri2(f2_add(top, C30));
    ull m1b = tri2(f2_add(bot, C15));
    ull m2b = tri2(f2_add(bot, C30));

    // s-sums: packed vertical add + scalar horizontal
    float2 s1p = f2_unpack(f2_add(m1t, m1b));
    float2 s2p = f2_unpack(f2_add(m2t, m2b));
    float s1 = s1p.x + s1p.y;
    float s2 = s2p.x + s2p.y;
    bool pick1 = (s1 >= s2);

    ull mt = pick1 ? m1t : m2t;
    ull mb = pick1 ? m1b : m2b;

    // t = m*v, den = sum(t), num = sum(t*v) — all packed until the last add
    ull tt = f2_mul(mt, top);
    ull tb = f2_mul(mb, bot);
    float2 denp = f2_unpack(f2_add(tt, tb));
    float den = denp.x + denp.y;
    float2 nump = f2_unpack(f2_fma(tb, bot, f2_mul(tt, top)));
    float num = nump.x + nump.y;

    // den==0 => num==0 => exact 0; no select needed
    return __fdividef(num, fmaxf(den, 1e-35f));
}

__global__ __launch_bounds__(256)
void fuzzy_pool_kernel(const float* __restrict__ x, float* __restrict__ out) {
    unsigned tid = blockIdx.x * blockDim.x + threadIdx.x;   // < 2,097,152

    // collapsed offsets: out = 4*tid, in = 16*tid - 8*(tid&15)
    unsigned in_off  = 16u * tid - 8u * (tid & 15u);
    unsigned out_off = 4u * tid;

    const ulonglong2* r0 = reinterpret_cast<const ulonglong2*>(x + in_off);
    const ulonglong2* r1 = reinterpret_cast<const ulonglong2*>(x + in_off + 128);

    // 4 independent 16B streaming loads; lanes arrive pre-packed
    ulonglong2 a0 = __ldcs(r0);
    ulonglong2 a1 = __ldcs(r0 + 1);
    ulonglong2 b0 = __ldcs(r1);
    ulonglong2 b1 = __ldcs(r1 + 1);

    const ull C15 = f2_pack(-1.5f, -1.5f);
    const ull C30 = f2_pack(-3.0f, -3.0f);

    float4 o;
    o.x = fuzzy_patch(a0.x, b0.x, C15, C30);
    o.y = fuzzy_patch(a0.y, b0.y, C15, C30);
    o.z = fuzzy_patch(a1.x, b1.x, C15, C30);
    o.w = fuzzy_patch(a1.y, b1.y, C15, C30);

    __stcs(reinterpret_cast<float4*>(out + out_off), o);
}

extern "C" void kernel_launch(void* const* d_in, const int* in_sizes, int n_in,
                              void* d_out, int out_size) {
    const float* x = (const float*)d_in[0];
    float* out = (float*)d_out;
    int threads = 256;
    int blocks = (N_OUT / 4) / threads;   // 8192 exactly
    fuzzy_pool_kernel<<<blocks, threads>>>(x, out);
}